// round 6
// baseline (speedup 1.0000x reference)
#include <cuda_runtime.h>
#include <cstdint>

// Problem constants
#define CB_K     512          // codebook size
#define CB_HALF  256
#define EMB_D    64           // embed dim
#define N_ROWS   65536        // 16*64*64
#define THREADS  512
#define N_CTA    (N_ROWS / THREADS)       // 128 CTAs, 1 row per thread, exact
#define Q_ELEMS  ((size_t)N_ROWS * EMB_D) // 1048576

// dynamic smem layout: e[512*64] f32 | c[512] f32 | red[512] f32
#define SMEM_FLOATS (CB_K * EMB_D + CB_K + THREADS)
#define SMEM_BYTES  (SMEM_FLOATS * 4)

__device__ float        g_partial[N_CTA];
__device__ unsigned int g_done;          // zero-init; self-resets each launch

// ---- packed f32x2 helpers (force FFMA2 in SASS) ----
__device__ __forceinline__ unsigned long long fma2(unsigned long long a,
                                                   unsigned long long b,
                                                   unsigned long long c) {
    unsigned long long r;
    asm("fma.rn.f32x2 %0, %1, %2, %3;" : "=l"(r) : "l"(a), "l"(b), "l"(c));
    return r;
}
__device__ __forceinline__ unsigned long long add2(unsigned long long a,
                                                   unsigned long long b) {
    unsigned long long r;
    asm("add.rn.f32x2 %0, %1, %2;" : "=l"(r) : "l"(a), "l"(b));
    return r;
}
__device__ __forceinline__ unsigned long long pk2(float lo, float hi) {
    unsigned long long r;
    asm("mov.b64 %0, {%1, %2};" : "=l"(r) : "f"(lo), "f"(hi));
    return r;
}
__device__ __forceinline__ float lo2(unsigned long long v) {
    return __uint_as_float((unsigned)(v & 0xffffffffull));
}
__device__ __forceinline__ float hi2(unsigned long long v) {
    return __uint_as_float((unsigned)(v >> 32));
}

// 512 threads/CTA, ONE row per thread (64 x-regs), 4 warps/SMSP for latency
// hiding. k-loop processes codes k and k+256 concurrently (independent
// accumulators + tails). Interleaved LDS/FFMA2 body (low register pressure).
__global__ void __launch_bounds__(THREADS, 1)
vq_fused_kernel(const float* __restrict__ x_g,
                const float* __restrict__ e_g,
                float* __restrict__ out) {
    extern __shared__ float smem[];
    float* se   = smem;                   // [512][64]
    float* sc   = smem + CB_K * EMB_D;    // [512] = |e_k|^2
    float* sred = sc + CB_K;              // [512] loss partials

    const int tid = threadIdx.x;

    // --- stage embedding into smem (coalesced float4) ---
    {
        float4* se4 = reinterpret_cast<float4*>(se);
        const float4* eg4 = reinterpret_cast<const float4*>(e_g);
        #pragma unroll
        for (int i = 0; i < (CB_K * EMB_D / 4) / THREADS; i++)
            se4[tid + i * THREADS] = eg4[tid + i * THREADS];
    }
    __syncthreads();

    // --- |e_k|^2 (one code per thread for tid<512) ---
    {
        const float* er = se + tid * EMB_D;
        float s = 0.f;
        #pragma unroll 16
        for (int d = 0; d < EMB_D; d++) s = __fmaf_rn(er[d], er[d], s);
        sc[tid] = s;
    }
    __syncthreads();

    // --- load this thread's x row into registers as 32 f32x2 pairs ---
    const int row = blockIdx.x * THREADS + tid;
    unsigned long long xx[32];
    {
        const float4* xr = reinterpret_cast<const float4*>(x_g + (size_t)row * EMB_D);
        #pragma unroll
        for (int i = 0; i < 16; i++) {
            float4 f = xr[i];
            xx[2 * i]     = pk2(f.x, f.y);
            xx[2 * i + 1] = pk2(f.z, f.w);
        }
    }

    // --- A = |x|^2 (same summation tree as all passing kernels) ---
    float A;
    {
        unsigned long long a0 = 0, a1 = 0, a2 = 0, a3 = 0;
        #pragma unroll
        for (int i = 0; i < 32; i += 4) {
            a0 = fma2(xx[i],     xx[i],     a0);
            a1 = fma2(xx[i + 1], xx[i + 1], a1);
            a2 = fma2(xx[i + 2], xx[i + 2], a2);
            a3 = fma2(xx[i + 3], xx[i + 3], a3);
        }
        unsigned long long s = add2(add2(a0, a2), add2(a1, a3));
        A = lo2(s) + hi2(s);
    }

    // --- argmin: codes k (half P) and k+256 (half Q) processed concurrently.
    // d_k = fl(fl(A - 2*dot_k) + C_k): exact reference association.
    float bestP = 3.4e38f, bestQ = 3.4e38f;
    int   bkP = 0, bkQ = CB_HALF;
    const ulonglong2* seu = reinterpret_cast<const ulonglong2*>(se);
    #pragma unroll 2
    for (int k = 0; k < CB_HALF; k++) {
        const ulonglong2* ep = seu + k * 16;
        const ulonglong2* eq = seu + (k + CB_HALF) * 16;
        unsigned long long pa0 = 0, pa1 = 0, pa2 = 0, pa3 = 0;
        unsigned long long qa0 = 0, qa1 = 0, qa2 = 0, qa3 = 0;
        #pragma unroll
        for (int i = 0; i < 16; i += 2) {
            ulonglong2 p0 = ep[i];
            ulonglong2 p1 = ep[i + 1];
            pa0 = fma2(xx[2 * i],     p0.x, pa0);
            pa1 = fma2(xx[2 * i + 1], p0.y, pa1);
            pa2 = fma2(xx[2 * i + 2], p1.x, pa2);
            pa3 = fma2(xx[2 * i + 3], p1.y, pa3);
            ulonglong2 q0 = eq[i];
            ulonglong2 q1 = eq[i + 1];
            qa0 = fma2(xx[2 * i],     q0.x, qa0);
            qa1 = fma2(xx[2 * i + 1], q0.y, qa1);
            qa2 = fma2(xx[2 * i + 2], q1.x, qa2);
            qa3 = fma2(xx[2 * i + 3], q1.y, qa3);
        }
        float ckP = sc[k];
        float ckQ = sc[k + CB_HALF];
        unsigned long long sP = add2(add2(pa0, pa2), add2(pa1, pa3));
        unsigned long long sQ = add2(add2(qa0, qa2), add2(qa1, qa3));
        float dP = lo2(sP) + hi2(sP);
        float dQ = lo2(sQ) + hi2(sQ);
        float eP = __fadd_rn(__fmaf_rn(-2.0f, dP, A), ckP);   // 2*dot exact
        float eQ = __fadd_rn(__fmaf_rn(-2.0f, dQ, A), ckQ);
        if (eP < bestP) { bestP = eP; bkP = k; }              // strict <
        if (eQ < bestQ) { bestQ = eQ; bkQ = k + CB_HALF; }
    }
    // cross-half merge: on ties keep the LOW half (lower index) -> strict <
    const int bk = (bestQ < bestP) ? bkQ : bkP;

    // --- epilogue: write quantized row + index, accumulate SSE for loss ---
    // Quantized region starts at out+1 => peel 3 scalars, 15 aligned float4, tail.
    float sse = 0.f;
    {
        const float* qr = se + bk * EMB_D;
        float* orow = out + 1 + (size_t)row * EMB_D;
        #pragma unroll
        for (int i = 0; i < 32; i++) {
            float d0 = qr[2 * i]     - lo2(xx[i]);
            float d1 = qr[2 * i + 1] - hi2(xx[i]);
            sse = __fmaf_rn(d0, d0, sse);
            sse = __fmaf_rn(d1, d1, sse);
        }
        orow[0] = qr[0]; orow[1] = qr[1]; orow[2] = qr[2];
        float4* ov = reinterpret_cast<float4*>(orow + 3);
        #pragma unroll
        for (int i = 0; i < 15; i++) {
            float4 q;
            q.x = qr[3 + 4 * i]; q.y = qr[4 + 4 * i];
            q.z = qr[5 + 4 * i]; q.w = qr[6 + 4 * i];
            ov[i] = q;
        }
        orow[63] = qr[63];
    }
    out[1 + Q_ELEMS + (size_t)row] = (float)bk;

    // --- CTA loss reduction (deterministic tree over 512 threads) ---
    sred[tid] = sse;
    __syncthreads();
    #pragma unroll
    for (int off = THREADS / 2; off > 0; off >>= 1) {
        if (tid < off) sred[tid] = sred[tid] + sred[tid + off];
        __syncthreads();
    }

    // --- last-CTA-done: deterministic final reduce, fused (no 2nd kernel) ---
    __shared__ unsigned int s_last;
    if (tid == 0) {
        g_partial[blockIdx.x] = sred[0];
        __threadfence();
        unsigned int prev = atomicAdd(&g_done, 1u);
        s_last = (prev == N_CTA - 1) ? 1u : 0u;
    }
    __syncthreads();
    if (s_last && tid == 0) {
        __threadfence();
        const volatile float* gp = g_partial;
        double acc = 0.0;
        #pragma unroll 4
        for (int i = 0; i < N_CTA; i++) acc += (double)gp[i];
        double mean = acc / (double)((size_t)N_ROWS * EMB_D);
        out[0] = (float)(1.25 * mean);   // q_latent + 0.25 * e_latent
        g_done = 0;                       // self-reset for next replay
        __threadfence();
    }
}

extern "C" void kernel_launch(void* const* d_in, const int* in_sizes, int n_in,
                              void* d_out, int out_size) {
    const float* x = (const float*)d_in[0];
    const float* e = (const float*)d_in[1];
    if (n_in >= 2 && in_sizes[0] == CB_K * EMB_D) {
        const float* t = x; x = e; e = t;
    }
    float* out = (float*)d_out;

    cudaFuncSetAttribute(vq_fused_kernel,
                         cudaFuncAttributeMaxDynamicSharedMemorySize, SMEM_BYTES);
    vq_fused_kernel<<<N_CTA, THREADS, SMEM_BYTES>>>(x, e, out);
}

// round 7
// speedup vs baseline: 1.1387x; 1.1387x over previous
#include <cuda_runtime.h>
#include <cstdint>

// Problem constants
#define CB_K     512          // codebook size
#define EMB_D    64           // embed dim
#define N_ROWS   65536        // 16*64*64
#define THREADS  256
#define ROWS_PER_THREAD 2
#define ROWS_PER_CTA (THREADS * ROWS_PER_THREAD)   // 512
#define N_CTA    (N_ROWS / ROWS_PER_CTA)           // 128
#define Q_ELEMS  ((size_t)N_ROWS * EMB_D)          // 1048576

// dynamic smem layout: e[512*64] f32 | c[512] f32 | red[256] f32
#define SMEM_FLOATS (CB_K * EMB_D + CB_K + THREADS)
#define SMEM_BYTES  (SMEM_FLOATS * 4)

__device__ float        g_partial[N_CTA];
__device__ unsigned int g_done;          // zero-init; self-resets each launch

// ---- packed f32x2 helpers (force FFMA2 in SASS) ----
__device__ __forceinline__ unsigned long long fma2(unsigned long long a,
                                                   unsigned long long b,
                                                   unsigned long long c) {
    unsigned long long r;
    asm("fma.rn.f32x2 %0, %1, %2, %3;" : "=l"(r) : "l"(a), "l"(b), "l"(c));
    return r;
}
__device__ __forceinline__ unsigned long long add2(unsigned long long a,
                                                   unsigned long long b) {
    unsigned long long r;
    asm("add.rn.f32x2 %0, %1, %2;" : "=l"(r) : "l"(a), "l"(b));
    return r;
}
__device__ __forceinline__ unsigned long long pk2(float lo, float hi) {
    unsigned long long r;
    asm("mov.b64 %0, {%1, %2};" : "=l"(r) : "f"(lo), "f"(hi));
    return r;
}
__device__ __forceinline__ float lo2(unsigned long long v) {
    return __uint_as_float((unsigned)(v & 0xffffffffull));
}
__device__ __forceinline__ float hi2(unsigned long long v) {
    return __uint_as_float((unsigned)(v >> 32));
}

// R3 body (proven fastest) + fused last-CTA loss reduction (proven -11us).
// One thread = TWO rows; e loaded from smem once per code, used for both rows.
__global__ void __launch_bounds__(THREADS, 1)
vq_fused_kernel(const float* __restrict__ x_g,
                const float* __restrict__ e_g,
                float* __restrict__ out) {
    extern __shared__ float smem[];
    float* se   = smem;                   // [512][64]
    float* sc   = smem + CB_K * EMB_D;    // [512] = |e_k|^2
    float* sred = sc + CB_K;              // [256] loss partials

    const int tid = threadIdx.x;

    // --- stage embedding into smem (coalesced float4) ---
    {
        float4* se4 = reinterpret_cast<float4*>(se);
        const float4* eg4 = reinterpret_cast<const float4*>(e_g);
        #pragma unroll
        for (int i = 0; i < (CB_K * EMB_D / 4) / THREADS; i++)
            se4[tid + i * THREADS] = eg4[tid + i * THREADS];
    }
    __syncthreads();

    // --- |e_k|^2 ---
    #pragma unroll
    for (int kk = 0; kk < CB_K / THREADS; kk++) {
        int k = tid + kk * THREADS;
        const float* er = se + k * EMB_D;
        float s = 0.f;
        #pragma unroll 16
        for (int d = 0; d < EMB_D; d++) s = __fmaf_rn(er[d], er[d], s);
        sc[k] = s;
    }
    __syncthreads();

    // --- load the two x rows into registers as f32x2 pairs ---
    const int row0 = blockIdx.x * ROWS_PER_CTA + tid;            // first row
    const int row1 = row0 + THREADS;                             // second row
    unsigned long long xa[32], xb[32];
    {
        const float4* xr0 = reinterpret_cast<const float4*>(x_g + (size_t)row0 * EMB_D);
        const float4* xr1 = reinterpret_cast<const float4*>(x_g + (size_t)row1 * EMB_D);
        #pragma unroll
        for (int i = 0; i < 16; i++) {
            float4 f = xr0[i];
            xa[2 * i]     = pk2(f.x, f.y);
            xa[2 * i + 1] = pk2(f.z, f.w);
            float4 g = xr1[i];
            xb[2 * i]     = pk2(g.x, g.y);
            xb[2 * i + 1] = pk2(g.z, g.w);
        }
    }

    // --- A = |x|^2 per row (same summation tree as the passing kernel) ---
    float A0, A1;
    {
        unsigned long long a0 = 0, a1 = 0, a2 = 0, a3 = 0;
        unsigned long long b0 = 0, b1 = 0, b2 = 0, b3 = 0;
        #pragma unroll
        for (int i = 0; i < 32; i += 4) {
            a0 = fma2(xa[i],     xa[i],     a0);
            a1 = fma2(xa[i + 1], xa[i + 1], a1);
            a2 = fma2(xa[i + 2], xa[i + 2], a2);
            a3 = fma2(xa[i + 3], xa[i + 3], a3);
            b0 = fma2(xb[i],     xb[i],     b0);
            b1 = fma2(xb[i + 1], xb[i + 1], b1);
            b2 = fma2(xb[i + 2], xb[i + 2], b2);
            b3 = fma2(xb[i + 3], xb[i + 3], b3);
        }
        unsigned long long s0 = add2(add2(a0, a2), add2(a1, a3));
        unsigned long long s1 = add2(add2(b0, b2), add2(b1, b3));
        A0 = lo2(s0) + hi2(s0);
        A1 = lo2(s1) + hi2(s1);
    }

    // --- argmin over codes: d_k = fl(fl(A - 2*B_k) + C_k)  (exact R3 loop) ---
    float best0 = 3.4e38f, best1 = 3.4e38f;
    int   bk0   = 0,       bk1   = 0;
    const ulonglong2* seu = reinterpret_cast<const ulonglong2*>(se);
    #pragma unroll 2
    for (int k = 0; k < CB_K; k++) {
        const ulonglong2* ek = seu + k * 16;   // 16 x ulonglong2 = 64 floats
        unsigned long long a0 = 0, a1 = 0, a2 = 0, a3 = 0;
        unsigned long long b0 = 0, b1 = 0, b2 = 0, b3 = 0;
        #pragma unroll
        for (int i = 0; i < 16; i += 2) {
            ulonglong2 e0 = ek[i];
            ulonglong2 e1 = ek[i + 1];
            a0 = fma2(xa[2 * i],     e0.x, a0);
            a1 = fma2(xa[2 * i + 1], e0.y, a1);
            a2 = fma2(xa[2 * i + 2], e1.x, a2);
            a3 = fma2(xa[2 * i + 3], e1.y, a3);
            b0 = fma2(xb[2 * i],     e0.x, b0);
            b1 = fma2(xb[2 * i + 1], e0.y, b1);
            b2 = fma2(xb[2 * i + 2], e1.x, b2);
            b3 = fma2(xb[2 * i + 3], e1.y, b3);
        }
        float ck = sc[k];
        unsigned long long s0 = add2(add2(a0, a2), add2(a1, a3));
        unsigned long long s1 = add2(add2(b0, b2), add2(b1, b3));
        float dot0 = lo2(s0) + hi2(s0);
        float dot1 = lo2(s1) + hi2(s1);
        // 2*dot is exact, so fmaf(-2,dot,A) == fl(A - 2*dot) bit-for-bit
        float dd0 = __fadd_rn(__fmaf_rn(-2.0f, dot0, A0), ck);
        float dd1 = __fadd_rn(__fmaf_rn(-2.0f, dot1, A1), ck);
        if (dd0 < best0) { best0 = dd0; bk0 = k; }   // strict < keeps lowest index
        if (dd1 < best1) { best1 = dd1; bk1 = k; }
    }

    // --- epilogue: write quantized rows + indices, accumulate SSE for loss ---
    // Quantized region starts at out+1 => peel 3 scalars, 15 aligned float4, tail.
    float sse = 0.f;
    {
        const float* qr = se + bk0 * EMB_D;
        float* orow = out + 1 + (size_t)row0 * EMB_D;
        #pragma unroll
        for (int i = 0; i < 32; i++) {
            float d0 = qr[2 * i]     - lo2(xa[i]);
            float d1 = qr[2 * i + 1] - hi2(xa[i]);
            sse = __fmaf_rn(d0, d0, sse);
            sse = __fmaf_rn(d1, d1, sse);
        }
        orow[0] = qr[0]; orow[1] = qr[1]; orow[2] = qr[2];
        float4* ov = reinterpret_cast<float4*>(orow + 3);
        #pragma unroll
        for (int i = 0; i < 15; i++) {
            float4 q;
            q.x = qr[3 + 4 * i]; q.y = qr[4 + 4 * i];
            q.z = qr[5 + 4 * i]; q.w = qr[6 + 4 * i];
            ov[i] = q;
        }
        orow[63] = qr[63];
    }
    {
        const float* qr = se + bk1 * EMB_D;
        float* orow = out + 1 + (size_t)row1 * EMB_D;
        #pragma unroll
        for (int i = 0; i < 32; i++) {
            float d0 = qr[2 * i]     - lo2(xb[i]);
            float d1 = qr[2 * i + 1] - hi2(xb[i]);
            sse = __fmaf_rn(d0, d0, sse);
            sse = __fmaf_rn(d1, d1, sse);
        }
        orow[0] = qr[0]; orow[1] = qr[1]; orow[2] = qr[2];
        float4* ov = reinterpret_cast<float4*>(orow + 3);
        #pragma unroll
        for (int i = 0; i < 15; i++) {
            float4 q;
            q.x = qr[3 + 4 * i]; q.y = qr[4 + 4 * i];
            q.z = qr[5 + 4 * i]; q.w = qr[6 + 4 * i];
            ov[i] = q;
        }
        orow[63] = qr[63];
    }
    out[1 + Q_ELEMS + (size_t)row0] = (float)bk0;
    out[1 + Q_ELEMS + (size_t)row1] = (float)bk1;

    // --- CTA loss reduction (deterministic tree) ---
    sred[tid] = sse;
    __syncthreads();
    #pragma unroll
    for (int off = THREADS / 2; off > 0; off >>= 1) {
        if (tid < off) sred[tid] = sred[tid] + sred[tid + off];
        __syncthreads();
    }

    // --- last-CTA-done: deterministic final reduce, fused (no 2nd kernel) ---
    __shared__ unsigned int s_last;
    if (tid == 0) {
        g_partial[blockIdx.x] = sred[0];
        __threadfence();
        unsigned int prev = atomicAdd(&g_done, 1u);
        s_last = (prev == N_CTA - 1) ? 1u : 0u;
    }
    __syncthreads();
    if (s_last && tid == 0) {
        __threadfence();
        const volatile float* gp = g_partial;
        double acc = 0.0;
        #pragma unroll 4
        for (int i = 0; i < N_CTA; i++) acc += (double)gp[i];
        double mean = acc / (double)((size_t)N_ROWS * EMB_D);
        out[0] = (float)(1.25 * mean);   // q_latent + 0.25 * e_latent
        g_done = 0;                       // self-reset for next replay
        __threadfence();
    }
}

extern "C" void kernel_launch(void* const* d_in, const int* in_sizes, int n_in,
                              void* d_out, int out_size) {
    const float* x = (const float*)d_in[0];
    const float* e = (const float*)d_in[1];
    if (n_in >= 2 && in_sizes[0] == CB_K * EMB_D) {
        const float* t = x; x = e; e = t;
    }
    float* out = (float*)d_out;

    cudaFuncSetAttribute(vq_fused_kernel,
                         cudaFuncAttributeMaxDynamicSharedMemorySize, SMEM_BYTES);
    vq_fused_kernel<<<N_CTA, THREADS, SMEM_BYTES>>>(x, e, out);
}

// round 8
// speedup vs baseline: 1.3210x; 1.1601x over previous
#include <cuda_runtime.h>
#include <cstdint>

// Problem constants
#define CB_K     512          // codebook size
#define EMB_D    64           // embed dim
#define N_ROWS   65536        // 16*64*64
#define THREADS  256
#define ROWS_PER_THREAD 2
#define ROWS_PER_CTA (THREADS * ROWS_PER_THREAD)   // 512
#define N_CTA    (N_ROWS / ROWS_PER_CTA)           // 128
#define Q_ELEMS  ((size_t)N_ROWS * EMB_D)          // 1048576

// dynamic smem layout: e[512*64] f32 | c[512] f32 | red[256] f32
#define SMEM_FLOATS (CB_K * EMB_D + CB_K + THREADS)
#define SMEM_BYTES  (SMEM_FLOATS * 4)

__device__ float g_partial[N_CTA];

// ---- packed f32x2 helpers (force FFMA2 in SASS) ----
__device__ __forceinline__ unsigned long long fma2(unsigned long long a,
                                                   unsigned long long b,
                                                   unsigned long long c) {
    unsigned long long r;
    asm("fma.rn.f32x2 %0, %1, %2, %3;" : "=l"(r) : "l"(a), "l"(b), "l"(c));
    return r;
}
__device__ __forceinline__ unsigned long long add2(unsigned long long a,
                                                   unsigned long long b) {
    unsigned long long r;
    asm("add.rn.f32x2 %0, %1, %2;" : "=l"(r) : "l"(a), "l"(b));
    return r;
}
__device__ __forceinline__ unsigned long long pk2(float lo, float hi) {
    unsigned long long r;
    asm("mov.b64 %0, {%1, %2};" : "=l"(r) : "f"(lo), "f"(hi));
    return r;
}
__device__ __forceinline__ float lo2(unsigned long long v) {
    return __uint_as_float((unsigned)(v & 0xffffffffull));
}
__device__ __forceinline__ float hi2(unsigned long long v) {
    return __uint_as_float((unsigned)(v >> 32));
}

// EXACT R3 main kernel (best measured config). One thread = TWO rows;
// e loaded from smem once per code, used against both rows.
__global__ void __launch_bounds__(THREADS, 1)
vq_main_kernel(const float* __restrict__ x_g,
               const float* __restrict__ e_g,
               float* __restrict__ out) {
    extern __shared__ float smem[];
    float* se   = smem;                   // [512][64]
    float* sc   = smem + CB_K * EMB_D;    // [512] = |e_k|^2
    float* sred = sc + CB_K;              // [256] loss partials

    const int tid = threadIdx.x;

    // --- stage embedding into smem (coalesced float4) ---
    {
        float4* se4 = reinterpret_cast<float4*>(se);
        const float4* eg4 = reinterpret_cast<const float4*>(e_g);
        #pragma unroll
        for (int i = 0; i < (CB_K * EMB_D / 4) / THREADS; i++)
            se4[tid + i * THREADS] = eg4[tid + i * THREADS];
    }
    __syncthreads();

    // --- |e_k|^2 ---
    #pragma unroll
    for (int kk = 0; kk < CB_K / THREADS; kk++) {
        int k = tid + kk * THREADS;
        const float* er = se + k * EMB_D;
        float s = 0.f;
        #pragma unroll 16
        for (int d = 0; d < EMB_D; d++) s = __fmaf_rn(er[d], er[d], s);
        sc[k] = s;
    }
    __syncthreads();

    // --- load the two x rows into registers as f32x2 pairs ---
    const int row0 = blockIdx.x * ROWS_PER_CTA + tid;            // first row
    const int row1 = row0 + THREADS;                             // second row
    unsigned long long xa[32], xb[32];
    {
        const float4* xr0 = reinterpret_cast<const float4*>(x_g + (size_t)row0 * EMB_D);
        const float4* xr1 = reinterpret_cast<const float4*>(x_g + (size_t)row1 * EMB_D);
        #pragma unroll
        for (int i = 0; i < 16; i++) {
            float4 f = xr0[i];
            xa[2 * i]     = pk2(f.x, f.y);
            xa[2 * i + 1] = pk2(f.z, f.w);
            float4 g = xr1[i];
            xb[2 * i]     = pk2(g.x, g.y);
            xb[2 * i + 1] = pk2(g.z, g.w);
        }
    }

    // --- A = |x|^2 per row ---
    float A0, A1;
    {
        unsigned long long a0 = 0, a1 = 0, a2 = 0, a3 = 0;
        unsigned long long b0 = 0, b1 = 0, b2 = 0, b3 = 0;
        #pragma unroll
        for (int i = 0; i < 32; i += 4) {
            a0 = fma2(xa[i],     xa[i],     a0);
            a1 = fma2(xa[i + 1], xa[i + 1], a1);
            a2 = fma2(xa[i + 2], xa[i + 2], a2);
            a3 = fma2(xa[i + 3], xa[i + 3], a3);
            b0 = fma2(xb[i],     xb[i],     b0);
            b1 = fma2(xb[i + 1], xb[i + 1], b1);
            b2 = fma2(xb[i + 2], xb[i + 2], b2);
            b3 = fma2(xb[i + 3], xb[i + 3], b3);
        }
        unsigned long long s0 = add2(add2(a0, a2), add2(a1, a3));
        unsigned long long s1 = add2(add2(b0, b2), add2(b1, b3));
        A0 = lo2(s0) + hi2(s0);
        A1 = lo2(s1) + hi2(s1);
    }

    // --- argmin over codes: d_k = fl(fl(A - 2*B_k) + C_k) ---
    float best0 = 3.4e38f, best1 = 3.4e38f;
    int   bk0   = 0,       bk1   = 0;
    const ulonglong2* seu = reinterpret_cast<const ulonglong2*>(se);
    #pragma unroll 2
    for (int k = 0; k < CB_K; k++) {
        const ulonglong2* ek = seu + k * 16;   // 16 x ulonglong2 = 64 floats
        unsigned long long a0 = 0, a1 = 0, a2 = 0, a3 = 0;
        unsigned long long b0 = 0, b1 = 0, b2 = 0, b3 = 0;
        #pragma unroll
        for (int i = 0; i < 16; i += 2) {
            ulonglong2 e0 = ek[i];
            ulonglong2 e1 = ek[i + 1];
            a0 = fma2(xa[2 * i],     e0.x, a0);
            a1 = fma2(xa[2 * i + 1], e0.y, a1);
            a2 = fma2(xa[2 * i + 2], e1.x, a2);
            a3 = fma2(xa[2 * i + 3], e1.y, a3);
            b0 = fma2(xb[2 * i],     e0.x, b0);
            b1 = fma2(xb[2 * i + 1], e0.y, b1);
            b2 = fma2(xb[2 * i + 2], e1.x, b2);
            b3 = fma2(xb[2 * i + 3], e1.y, b3);
        }
        float ck = sc[k];
        unsigned long long s0 = add2(add2(a0, a2), add2(a1, a3));
        unsigned long long s1 = add2(add2(b0, b2), add2(b1, b3));
        float dot0 = lo2(s0) + hi2(s0);
        float dot1 = lo2(s1) + hi2(s1);
        // 2*dot is exact, so fmaf(-2,dot,A) == fl(A - 2*dot) bit-for-bit
        float dd0 = __fadd_rn(__fmaf_rn(-2.0f, dot0, A0), ck);
        float dd1 = __fadd_rn(__fmaf_rn(-2.0f, dot1, A1), ck);
        if (dd0 < best0) { best0 = dd0; bk0 = k; }   // strict < keeps lowest index
        if (dd1 < best1) { best1 = dd1; bk1 = k; }
    }

    // --- epilogue: write quantized rows + indices, accumulate SSE for loss ---
    float sse = 0.f;
    {
        const float* qr = se + bk0 * EMB_D;
        float* orow = out + 1 + (size_t)row0 * EMB_D;
        #pragma unroll
        for (int i = 0; i < 32; i++) {
            float d0 = qr[2 * i]     - lo2(xa[i]);
            float d1 = qr[2 * i + 1] - hi2(xa[i]);
            sse = __fmaf_rn(d0, d0, sse);
            sse = __fmaf_rn(d1, d1, sse);
        }
        orow[0] = qr[0]; orow[1] = qr[1]; orow[2] = qr[2];
        float4* ov = reinterpret_cast<float4*>(orow + 3);
        #pragma unroll
        for (int i = 0; i < 15; i++) {
            float4 q;
            q.x = qr[3 + 4 * i]; q.y = qr[4 + 4 * i];
            q.z = qr[5 + 4 * i]; q.w = qr[6 + 4 * i];
            ov[i] = q;
        }
        orow[63] = qr[63];
    }
    {
        const float* qr = se + bk1 * EMB_D;
        float* orow = out + 1 + (size_t)row1 * EMB_D;
        #pragma unroll
        for (int i = 0; i < 32; i++) {
            float d0 = qr[2 * i]     - lo2(xb[i]);
            float d1 = qr[2 * i + 1] - hi2(xb[i]);
            sse = __fmaf_rn(d0, d0, sse);
            sse = __fmaf_rn(d1, d1, sse);
        }
        orow[0] = qr[0]; orow[1] = qr[1]; orow[2] = qr[2];
        float4* ov = reinterpret_cast<float4*>(orow + 3);
        #pragma unroll
        for (int i = 0; i < 15; i++) {
            float4 q;
            q.x = qr[3 + 4 * i]; q.y = qr[4 + 4 * i];
            q.z = qr[5 + 4 * i]; q.w = qr[6 + 4 * i];
            ov[i] = q;
        }
        orow[63] = qr[63];
    }
    out[1 + Q_ELEMS + (size_t)row0] = (float)bk0;
    out[1 + Q_ELEMS + (size_t)row1] = (float)bk1;

    // --- CTA loss reduction (deterministic tree) ---
    sred[tid] = sse;
    __syncthreads();
    #pragma unroll
    for (int off = THREADS / 2; off > 0; off >>= 1) {
        if (tid < off) sred[tid] = sred[tid] + sred[tid + off];
        __syncthreads();
    }
    if (tid == 0) g_partial[blockIdx.x] = sred[0];
}

// Final deterministic reduce over 128 CTA partials: loss = 1.25 * SSE / (N*D)
__global__ void vq_reduce_kernel(float* __restrict__ out) {
    __shared__ double sd[N_CTA];
    int tid = threadIdx.x;
    sd[tid] = (double)g_partial[tid];
    __syncthreads();
    #pragma unroll
    for (int off = N_CTA / 2; off > 0; off >>= 1) {
        if (tid < off) sd[tid] = sd[tid] + sd[tid + off];
        __syncthreads();
    }
    if (tid == 0) {
        double mean = sd[0] / (double)((size_t)N_ROWS * EMB_D);
        out[0] = (float)(1.25 * mean);   // q_latent + 0.25 * e_latent
    }
}

extern "C" void kernel_launch(void* const* d_in, const int* in_sizes, int n_in,
                              void* d_out, int out_size) {
    const float* x = (const float*)d_in[0];
    const float* e = (const float*)d_in[1];
    if (n_in >= 2 && in_sizes[0] == CB_K * EMB_D) {
        const float* t = x; x = e; e = t;
    }
    float* out = (float*)d_out;

    cudaFuncSetAttribute(vq_main_kernel,
                         cudaFuncAttributeMaxDynamicSharedMemorySize, SMEM_BYTES);
    vq_main_kernel<<<N_CTA, THREADS, SMEM_BYTES>>>(x, e, out);
    vq_reduce_kernel<<<1, N_CTA>>>(out);
}